// round 6
// baseline (speedup 1.0000x reference)
#include <cuda_runtime.h>
#include <math.h>
#include <stdint.h>

// Problem constants
#define BB   16
#define NN   2048
#define CIN  64
#define CC   256
#define MTOT (BB*NN)   // 32768

// ---------------- scratch (device globals; no allocation allowed) ----------------
__device__ float g_h[MTOT*CC];
__device__ float g_q[MTOT*CC];
__device__ float g_v[MTOT*CC];
__device__ float g_u[MTOT*CC];
__device__ float g_attn[(size_t)BB*NN*NN];   // 256 MiB attention matrix
__device__ float g_bnscale[3*CC];
__device__ float g_bnshift[3*CC];

// ---------------- BN precompute ----------------
__global__ void bn_prep(const float* __restrict__ g1, const float* __restrict__ b1,
                        const float* __restrict__ m1, const float* __restrict__ v1,
                        const float* __restrict__ g2, const float* __restrict__ b2,
                        const float* __restrict__ m2, const float* __restrict__ v2,
                        const float* __restrict__ g3, const float* __restrict__ b3,
                        const float* __restrict__ m3, const float* __restrict__ v3,
                        const float* __restrict__ bt)
{
    int c = threadIdx.x;
    float s;
    s = g1[c] * rsqrtf(v1[c] + 1e-5f);
    g_bnscale[c]       = s; g_bnshift[c]       = b1[c] - m1[c]*s;
    s = g2[c] * rsqrtf(v2[c] + 1e-5f);
    g_bnscale[256 + c] = s; g_bnshift[256 + c] = b2[c] - m2[c]*s;
    s = g3[c] * rsqrtf(v3[c] + 1e-5f);
    g_bnscale[512 + c] = s; g_bnshift[512 + c] = (bt[c] - m3[c])*s + b3[c];
}

__device__ __forceinline__ uint32_t cvt_tf32(float x) {
    uint32_t u;
    asm("cvt.rna.tf32.f32 %0, %1;" : "=r"(u) : "f"(x));
    return u;
}

__device__ __forceinline__ float4 cvt4(float4 v) {
    float4 o;
    o.x = __uint_as_float(cvt_tf32(v.x));
    o.y = __uint_as_float(cvt_tf32(v.y));
    o.z = __uint_as_float(cvt_tf32(v.z));
    o.w = __uint_as_float(cvt_tf32(v.w));
    return o;
}

// ---------------- tensor-core tiled GEMM (tf32 mma.sync, register-staged pipe) ----
// C[m,n] = sum_k opA(A)[m,k] * opB(B)[n,k]
// BM=128, BN=256, BK=16; 256 threads = 8 warps (2 x 4), warp tile 64x64
//   = 4i x 8j of m16n8k8 (2 k8 steps per BK tile).
// smem holds tf32-rounded bits (converted at STS); inner loop = LDS + HMMA only.
//   A non-trans: [row][k] stride 20 (2560 f);  A trans: [k][row] stride 136 (2176 f)
//   B non-trans: [n][k]  stride 20 (5120 f);  B trans: [k][n]  stride 264 (4224 f)
// EPI: 0 plain; 1 relu(acc*p0[c]+p1[c]); 2 acc+p0[c];
//      4 p2[r,c] - acc*rscale[r]  with rscale computed IN-CTA from raw A (attn)
template<int EPI, bool ATRANS, bool BTRANS>
__global__ __launch_bounds__(256)
void gemm_tc(const float* __restrict__ A, const float* __restrict__ B,
             float* __restrict__ C, int K,
             int lda, int ldb, int ldc,
             long long sA, long long sB, long long sC,
             const float* __restrict__ p0, const float* __restrict__ p1,
             const float* __restrict__ p2)
{
    constexpr int ASZ = ATRANS ? 16 * 136 : 128 * 20;   // 2176 : 2560
    constexpr int BSZ = BTRANS ? 16 * 264 : 256 * 20;   // 4224 : 5120
    extern __shared__ float smem[];
    float* As0 = smem;
    float* As1 = smem + ASZ;
    float* Bs0 = smem + 2 * ASZ;
    float* Bs1 = smem + 2 * ASZ + BSZ;

    const int z = blockIdx.z;
    A += (long long)z * sA;
    B += (long long)z * sB;

    const int t    = threadIdx.x;
    const int lane = t & 31;
    const int wid  = t >> 5;
    const int wm   = wid >> 2;      // 0..1   (64-row slab)
    const int wn   = wid & 3;       // 0..3   (64-col slab)
    const int grp  = lane >> 2;     // 0..7
    const int qid  = lane & 3;      // 0..3
    const int m0   = blockIdx.y * 128;
    const int n0   = blockIdx.x * 256;

    // ---- staging: A = 2 float4 / thread, B = 4 float4 / thread ----
    const float* aP[2];
    const float* bP[4];
    int aOff[2], bOff[4];
    long long aStep, bStep;
    if (!ATRANS) {
        aStep = 16;
#pragma unroll
        for (int p = 0; p < 2; p++) {
            int row = (t >> 2) + 64 * p, kq = t & 3;
            aP[p]   = A + (long long)(m0 + row) * lda + kq * 4;
            aOff[p] = row * 20 + kq * 4;
        }
    } else {
        aStep = (long long)lda * 16;
#pragma unroll
        for (int p = 0; p < 2; p++) {
            int kk = (t >> 5) + 8 * p, mq = t & 31;
            aP[p]   = A + (long long)kk * lda + m0 + mq * 4;
            aOff[p] = kk * 136 + mq * 4;
        }
    }
    if (!BTRANS) {
        bStep = 16;
#pragma unroll
        for (int p = 0; p < 4; p++) {
            int row = (t >> 2) + 64 * p, kq = t & 3;
            bP[p]   = B + (long long)(n0 + row) * ldb + kq * 4;
            bOff[p] = row * 20 + kq * 4;
        }
    } else {
        bStep = (long long)ldb * 16;
#pragma unroll
        for (int p = 0; p < 4; p++) {
            int kk = (t >> 6) + 4 * p, nq = t & 63;
            bP[p]   = B + (long long)kk * ldb + n0 + nq * 4;
            bOff[p] = kk * 264 + nq * 4;
        }
    }

    float acc[4][8][4];
#pragma unroll
    for (int i = 0; i < 4; i++)
#pragma unroll
        for (int j = 0; j < 8; j++)
#pragma unroll
            for (int e = 0; e < 4; e++) acc[i][j][e] = 0.f;

    float4 stA[2], stB[4];
    float colacc[4] = {0.f, 0.f, 0.f, 0.f};   // EPI4: partial column sums of attn

#define LDG_TILE(kit)                                                    \
    {                                                                    \
        long long ao = (long long)(kit) * aStep;                         \
        long long bo = (long long)(kit) * bStep;                         \
        stA[0] = *(const float4*)(aP[0] + ao);                           \
        stA[1] = *(const float4*)(aP[1] + ao);                           \
        stB[0] = *(const float4*)(bP[0] + bo);                           \
        stB[1] = *(const float4*)(bP[1] + bo);                           \
        stB[2] = *(const float4*)(bP[2] + bo);                           \
        stB[3] = *(const float4*)(bP[3] + bo);                           \
    }

#define STS_TILE(Aw, Bw)                                                 \
    {                                                                    \
        if (EPI == 4) {                                                  \
            colacc[0] += stA[0].x + stA[1].x;                            \
            colacc[1] += stA[0].y + stA[1].y;                            \
            colacc[2] += stA[0].z + stA[1].z;                            \
            colacc[3] += stA[0].w + stA[1].w;                            \
        }                                                                \
        *(float4*)&(Aw)[aOff[0]] = cvt4(stA[0]);                         \
        *(float4*)&(Aw)[aOff[1]] = cvt4(stA[1]);                         \
        *(float4*)&(Bw)[bOff[0]] = cvt4(stB[0]);                         \
        *(float4*)&(Bw)[bOff[1]] = cvt4(stB[1]);                         \
        *(float4*)&(Bw)[bOff[2]] = cvt4(stB[2]);                         \
        *(float4*)&(Bw)[bOff[3]] = cvt4(stB[3]);                         \
    }

    // prologue
    LDG_TILE(0)
    STS_TILE(As0, Bs0)
    __syncthreads();

    const int kIters = K / 16;
    for (int kit = 0, buf = 0; kit < kIters; kit++, buf ^= 1) {
        const bool have_next = (kit + 1) < kIters;
        if (have_next) LDG_TILE(kit + 1)

        const float* Ab = buf ? As1 : As0;
        const float* Bb = buf ? Bs1 : Bs0;
#pragma unroll
        for (int ks = 0; ks < 16; ks += 8) {
            uint32_t a[4][4], b[8][2];
#pragma unroll
            for (int i = 0; i < 4; i++) {
                int rb = wm * 64 + i * 16 + grp;
                if (!ATRANS) {
                    a[i][0] = __float_as_uint(Ab[(rb    ) * 20 + ks + qid]);
                    a[i][1] = __float_as_uint(Ab[(rb + 8) * 20 + ks + qid]);
                    a[i][2] = __float_as_uint(Ab[(rb    ) * 20 + ks + 4 + qid]);
                    a[i][3] = __float_as_uint(Ab[(rb + 8) * 20 + ks + 4 + qid]);
                } else {
                    a[i][0] = __float_as_uint(Ab[(ks + qid    ) * 136 + rb]);
                    a[i][1] = __float_as_uint(Ab[(ks + qid    ) * 136 + rb + 8]);
                    a[i][2] = __float_as_uint(Ab[(ks + qid + 4) * 136 + rb]);
                    a[i][3] = __float_as_uint(Ab[(ks + qid + 4) * 136 + rb + 8]);
                }
            }
#pragma unroll
            for (int j = 0; j < 8; j++) {
                int nb = wn * 64 + j * 8 + grp;
                if (!BTRANS) {
                    b[j][0] = __float_as_uint(Bb[nb * 20 + ks + qid]);
                    b[j][1] = __float_as_uint(Bb[nb * 20 + ks + 4 + qid]);
                } else {
                    b[j][0] = __float_as_uint(Bb[(ks + qid    ) * 264 + nb]);
                    b[j][1] = __float_as_uint(Bb[(ks + qid + 4) * 264 + nb]);
                }
            }
#pragma unroll
            for (int i = 0; i < 4; i++)
#pragma unroll
                for (int j = 0; j < 8; j++) {
                    asm volatile(
                        "mma.sync.aligned.m16n8k8.row.col.f32.tf32.tf32.f32 "
                        "{%0,%1,%2,%3}, {%4,%5,%6,%7}, {%8,%9}, {%0,%1,%2,%3};\n"
                        : "+f"(acc[i][j][0]), "+f"(acc[i][j][1]),
                          "+f"(acc[i][j][2]), "+f"(acc[i][j][3])
                        : "r"(a[i][0]), "r"(a[i][1]), "r"(a[i][2]), "r"(a[i][3]),
                          "r"(b[j][0]), "r"(b[j][1]));
                }
        }
        if (have_next) {
            if (buf) STS_TILE(As0, Bs0)
            else     STS_TILE(As1, Bs1)
        }
        __syncthreads();
    }
#undef LDG_TILE
#undef STS_TILE

    // ---- EPI4: reduce column sums -> rscale in smem ----
    float* rsc = As0 + 1024;   // reuse A buffer 0 after final barrier
    if (EPI == 4) {
        float* red = As0;      // 8 groups x 128 columns
        const int g  = t >> 5;
        const int cq = (t & 31) * 4;
        red[g * 128 + cq + 0] = colacc[0];
        red[g * 128 + cq + 1] = colacc[1];
        red[g * 128 + cq + 2] = colacc[2];
        red[g * 128 + cq + 3] = colacc[3];
        __syncthreads();
        if (t < 128) {
            float s = 0.f;
#pragma unroll
            for (int gg = 0; gg < 8; gg++) s += red[gg * 128 + t];
            rsc[t] = 1.f / (1e-9f + s);
        }
        __syncthreads();
    }

    // ---- epilogue ----
    float* Cz = C + (long long)z * sC;
#pragma unroll
    for (int i = 0; i < 4; i++) {
        int r0 = m0 + wm * 64 + i * 16 + grp;
        int r1 = r0 + 8;
#pragma unroll
        for (int j = 0; j < 8; j++) {
            int c = n0 + wn * 64 + j * 8 + qid * 2;
            float d0 = acc[i][j][0], d1 = acc[i][j][1];
            float d2 = acc[i][j][2], d3 = acc[i][j][3];
            float2 o0, o1;
            if (EPI == 0) {
                o0 = make_float2(d0, d1);
                o1 = make_float2(d2, d3);
            } else if (EPI == 1) {
                float s0 = p0[c], s1 = p0[c+1], h0 = p1[c], h1 = p1[c+1];
                o0.x = fmaxf(d0 * s0 + h0, 0.f);
                o0.y = fmaxf(d1 * s1 + h1, 0.f);
                o1.x = fmaxf(d2 * s0 + h0, 0.f);
                o1.y = fmaxf(d3 * s1 + h1, 0.f);
            } else if (EPI == 2) {
                float h0 = p0[c], h1 = p0[c+1];
                o0 = make_float2(d0 + h0, d1 + h1);
                o1 = make_float2(d2 + h0, d3 + h1);
            } else { // EPI == 4 : u = h - acc*rscale[row]
                float rsa = rsc[r0 - m0];
                float rsb = rsc[r1 - m0];
                const float* hpz = p2 + (long long)z * sC;
                o0.x = hpz[(long long)r0 * ldc + c    ] - d0 * rsa;
                o0.y = hpz[(long long)r0 * ldc + c + 1] - d1 * rsa;
                o1.x = hpz[(long long)r1 * ldc + c    ] - d2 * rsb;
                o1.y = hpz[(long long)r1 * ldc + c + 1] - d3 * rsb;
            }
            *(float2*)&Cz[(long long)r0 * ldc + c] = o0;
            *(float2*)&Cz[(long long)r1 * ldc + c] = o1;
        }
    }
}

// ---------------- softmax over last dim, one block per row (2048 elems) ----------
__global__ void softmax_rows(float* __restrict__ attn)
{
    __shared__ float red[256];
    float* p = attn + (long long)blockIdx.x * NN;
    const int t = threadIdx.x;
    float v[8];
    float mx = -1e30f;
#pragma unroll
    for (int i = 0; i < 8; i++) { v[i] = p[t + i*256]; mx = fmaxf(mx, v[i]); }
    red[t] = mx; __syncthreads();
    for (int s = 128; s > 0; s >>= 1) {
        if (t < s) red[t] = fmaxf(red[t], red[t + s]);
        __syncthreads();
    }
    mx = red[0]; __syncthreads();
    float sum = 0.f;
#pragma unroll
    for (int i = 0; i < 8; i++) { v[i] = __expf(v[i] - mx); sum += v[i]; }
    red[t] = sum; __syncthreads();
    for (int s = 128; s > 0; s >>= 1) {
        if (t < s) red[t] += red[t + s];
        __syncthreads();
    }
    float inv = 1.f / red[0];
#pragma unroll
    for (int i = 0; i < 8; i++) p[t + i*256] = v[i] * inv;
}

// ---------------- out[b,c,i] = h[b,i,c] + t[b,i,c]  (transpose via smem) ---------
__global__ void trans_add(const float* __restrict__ h, const float* __restrict__ tt,
                          float* __restrict__ out)
{
    __shared__ float sh[32][33];
    const int b  = blockIdx.z;
    const int i0 = blockIdx.x * 32, c0 = blockIdx.y * 32;
    const int tx = threadIdx.x, ty = threadIdx.y;   // 32 x 8
#pragma unroll
    for (int r = 0; r < 4; r++) {
        int i = i0 + ty + r * 8;
        long long idx = ((long long)b * NN + i) * CC + c0 + tx;
        sh[ty + r * 8][tx] = h[idx] + tt[idx];
    }
    __syncthreads();
#pragma unroll
    for (int r = 0; r < 4; r++) {
        int c = c0 + ty + r * 8;
        out[((long long)b * CC + c) * NN + i0 + tx] = sh[tx][ty + r * 8];
    }
}

// ==================================================================================
extern "C" void kernel_launch(void* const* d_in, const int* in_sizes, int n_in,
                              void* d_out, int out_size)
{
    const float* x   = (const float*)d_in[0];
    const float* w1  = (const float*)d_in[1];
    const float* w2  = (const float*)d_in[2];
    const float* wqk = (const float*)d_in[3];
    const float* wv  = (const float*)d_in[4];
    const float* bv  = (const float*)d_in[5];
    const float* wt  = (const float*)d_in[6];
    const float* bt  = (const float*)d_in[7];
    const float* bn1g = (const float*)d_in[8],  *bn1b = (const float*)d_in[9];
    const float* bn1m = (const float*)d_in[10], *bn1v = (const float*)d_in[11];
    const float* bn2g = (const float*)d_in[12], *bn2b = (const float*)d_in[13];
    const float* bn2m = (const float*)d_in[14], *bn2v = (const float*)d_in[15];
    const float* bn3g = (const float*)d_in[16], *bn3b = (const float*)d_in[17];
    const float* bn3m = (const float*)d_in[18], *bn3v = (const float*)d_in[19];

    float *h, *q, *v, *u, *attn, *bns, *bnh;
    cudaGetSymbolAddress((void**)&h, g_h);
    cudaGetSymbolAddress((void**)&q, g_q);
    cudaGetSymbolAddress((void**)&v, g_v);
    cudaGetSymbolAddress((void**)&u, g_u);
    cudaGetSymbolAddress((void**)&attn, g_attn);
    cudaGetSymbolAddress((void**)&bns, g_bnscale);
    cudaGetSymbolAddress((void**)&bnh, g_bnshift);

    // dynamic smem sizes (bytes): non-trans/non-trans vs trans/trans
    const int S_NN = (2 * 2560 + 2 * 5120) * 4;   // 61440
    const int S_TT = (2 * 2176 + 2 * 4224) * 4;   // 51200
    cudaFuncSetAttribute(gemm_tc<0, false, false>,
                         cudaFuncAttributeMaxDynamicSharedMemorySize, S_NN);
    cudaFuncSetAttribute(gemm_tc<1, false, false>,
                         cudaFuncAttributeMaxDynamicSharedMemorySize, S_NN);
    cudaFuncSetAttribute(gemm_tc<2, false, false>,
                         cudaFuncAttributeMaxDynamicSharedMemorySize, S_NN);
    cudaFuncSetAttribute(gemm_tc<4, true, true>,
                         cudaFuncAttributeMaxDynamicSharedMemorySize, S_TT);

    bn_prep<<<1, 256>>>(bn1g, bn1b, bn1m, bn1v,
                        bn2g, bn2b, bn2m, bn2v,
                        bn3g, bn3b, bn3m, bn3v, bt);

    // h1 = relu(bn1(x @ w1^T))   (into q as temp)
    gemm_tc<1, false, false><<<dim3(1, MTOT/128, 1), 256, S_NN>>>(
        x, w1, q, CIN, CIN, CIN, CC, 0, 0, 0, bns, bnh, nullptr);

    // h = relu(bn2(h1 @ w2^T))
    gemm_tc<1, false, false><<<dim3(1, MTOT/128, 1), 256, S_NN>>>(
        q, w2, h, CC, CC, CC, CC, 0, 0, 0, bns + 256, bnh + 256, nullptr);

    // q = h @ wqk^T
    gemm_tc<0, false, false><<<dim3(1, MTOT/128, 1), 256, S_NN>>>(
        h, wqk, q, CC, CC, CC, CC, 0, 0, 0, nullptr, nullptr, nullptr);

    // v = h @ wv^T + bv
    gemm_tc<2, false, false><<<dim3(1, MTOT/128, 1), 256, S_NN>>>(
        h, wv, v, CC, CC, CC, CC, 0, 0, 0, bv, nullptr, nullptr);

    // energy[b,i,j] = q[b,i,:] . q[b,j,:]   (batched)
    gemm_tc<0, false, false><<<dim3(NN/256, NN/128, BB), 256, S_NN>>>(
        q, q, attn, CC, CC, CC, NN,
        (long long)NN*CC, (long long)NN*CC, (long long)NN*NN,
        nullptr, nullptr, nullptr);

    // row softmax
    softmax_rows<<<MTOT, 256>>>(attn);

    // u[b,j,c] = h - (sum_i attn[i,j] v[i,c]) / (eps + sum_i attn[i,j])
    // colsum fused in-kernel from raw staged attn values
    gemm_tc<4, true, true><<<dim3(1, NN/128, BB), 256, S_TT>>>(
        attn, v, u, NN, NN, CC, CC,
        (long long)NN*NN, (long long)NN*CC, (long long)NN*CC,
        nullptr, nullptr, h);

    // t = relu(bn3(u @ wt^T + bt))   (into q as temp; bt folded into shift)
    gemm_tc<1, false, false><<<dim3(1, MTOT/128, 1), 256, S_NN>>>(
        u, wt, q, CC, CC, CC, CC, 0, 0, 0, bns + 512, bnh + 512, nullptr);

    // out[b,c,i] = h + t, transposed
    trans_add<<<dim3(NN/32, CC/32, BB), dim3(32, 8)>>>(h, q, (float*)d_out);
}

// round 7
// speedup vs baseline: 1.1968x; 1.1968x over previous
#include <cuda_runtime.h>
#include <math.h>
#include <stdint.h>

// Problem constants
#define BB   16
#define NN   2048
#define CIN  64
#define CC   256
#define MTOT (BB*NN)   // 32768
#define NBLK 16        // NN/128
#define NPAIRS 136     // NBLK*(NBLK+1)/2

// dynamic smem: 4 buffers x 2560 floats + 128 rsc
#define SMEMB ((4*2560 + 128) * 4)

// ---------------- scratch (device globals; no allocation allowed) ----------------
__device__ float g_h[MTOT*CC];
__device__ float g_q[MTOT*CC];
__device__ float g_v[MTOT*CC];
__device__ float g_u[MTOT*CC];
__device__ float g_attn[(size_t)BB*NN*NN];   // 256 MiB attention matrix
__device__ float g_bnscale[3*CC];
__device__ float g_bnshift[3*CC];

// ---------------- BN precompute ----------------
__global__ void bn_prep(const float* __restrict__ g1, const float* __restrict__ b1,
                        const float* __restrict__ m1, const float* __restrict__ v1,
                        const float* __restrict__ g2, const float* __restrict__ b2,
                        const float* __restrict__ m2, const float* __restrict__ v2,
                        const float* __restrict__ g3, const float* __restrict__ b3,
                        const float* __restrict__ m3, const float* __restrict__ v3,
                        const float* __restrict__ bt)
{
    int c = threadIdx.x;
    float s;
    s = g1[c] * rsqrtf(v1[c] + 1e-5f);
    g_bnscale[c]       = s; g_bnshift[c]       = b1[c] - m1[c]*s;
    s = g2[c] * rsqrtf(v2[c] + 1e-5f);
    g_bnscale[256 + c] = s; g_bnshift[256 + c] = b2[c] - m2[c]*s;
    s = g3[c] * rsqrtf(v3[c] + 1e-5f);
    g_bnscale[512 + c] = s; g_bnshift[512 + c] = (bt[c] - m3[c])*s + b3[c];
}

__device__ __forceinline__ uint32_t cvt_tf32(float x) {
    uint32_t u;
    asm("cvt.rna.tf32.f32 %0, %1;" : "=r"(u) : "f"(x));
    return u;
}

__device__ __forceinline__ float4 cvt4(float4 v) {
    float4 o;
    o.x = __uint_as_float(cvt_tf32(v.x));
    o.y = __uint_as_float(cvt_tf32(v.y));
    o.z = __uint_as_float(cvt_tf32(v.z));
    o.w = __uint_as_float(cvt_tf32(v.w));
    return o;
}

// ---------------- tensor-core tiled GEMM (tf32 mma.sync, register-staged pipe) ----
// C[m,n] = sum_k opA(A)[m,k] * opB(B)[n,k]
// BM=BN=128, BK=16; 256 threads = 8 warps (2x4), warp tile 64x32 = 4x4 m16n8k8.
// smem holds tf32-rounded bits (converted at STS); inner loop = LDS + HMMA only.
//   non-trans operand: [row][k]  stride 20
//   trans operand:     [k][row]  stride 136
// EPI: 0 plain; 1 relu(acc*p0[c]+p1[c]); 2 acc+p0[c];
//      4 p2[r,c] - acc*rscale[r]  with rscale computed IN-CTA from raw A (attn);
//      5 symmetric-output: blockIdx.x = upper-tri pair (bi<=bj); store block and,
//        if off-diagonal, its transpose (smem-staged, coalesced).
template<int EPI, bool ATRANS, bool BTRANS>
__global__ __launch_bounds__(256, 2)
void gemm_tc(const float* __restrict__ A, const float* __restrict__ B,
             float* __restrict__ C, int K,
             int lda, int ldb, int ldc,
             long long sA, long long sB, long long sC,
             const float* __restrict__ p0, const float* __restrict__ p1,
             const float* __restrict__ p2)
{
    extern __shared__ float smem[];
    float* As0 = smem;
    float* As1 = smem + 2560;
    float* Bs0 = smem + 2 * 2560;
    float* Bs1 = smem + 3 * 2560;
    float* rsc = smem + 4 * 2560;   // EPI4: per-row 1/(eps+colsum)

    const int z = blockIdx.z;
    A += (long long)z * sA;
    B += (long long)z * sB;

    const int t    = threadIdx.x;
    const int lane = t & 31;
    const int wid  = t >> 5;
    const int wm   = wid >> 2;      // 0..1
    const int wn   = wid & 3;       // 0..3
    const int grp  = lane >> 2;     // 0..7
    const int qid  = lane & 3;      // 0..3

    int m0, n0;
    if (EPI == 5) {
        int rem = blockIdx.x, bi = 0;
        while (rem >= NBLK - bi) { rem -= NBLK - bi; bi++; }
        m0 = bi * 128;
        n0 = (bi + rem) * 128;
    } else {
        m0 = blockIdx.y * 128;
        n0 = blockIdx.x * 128;
    }

    const int idx0 = t, idx1 = t + 256;

    // per-thread global base pointers and per-16-k strides
    const long long aStep = ATRANS ? (long long)lda * 16 : 16;
    const long long bStep = BTRANS ? (long long)ldb * 16 : 16;
    const float* aP0 = A + (ATRANS ? (long long)(idx0 >> 5) * lda + m0 + (idx0 & 31) * 4
                                   : (long long)(m0 + (idx0 >> 2)) * lda + (idx0 & 3) * 4);
    const float* aP1 = A + (ATRANS ? (long long)(idx1 >> 5) * lda + m0 + (idx1 & 31) * 4
                                   : (long long)(m0 + (idx1 >> 2)) * lda + (idx1 & 3) * 4);
    const float* bP0 = B + (BTRANS ? (long long)(idx0 >> 5) * ldb + n0 + (idx0 & 31) * 4
                                   : (long long)(n0 + (idx0 >> 2)) * ldb + (idx0 & 3) * 4);
    const float* bP1 = B + (BTRANS ? (long long)(idx1 >> 5) * ldb + n0 + (idx1 & 31) * 4
                                   : (long long)(n0 + (idx1 >> 2)) * ldb + (idx1 & 3) * 4);

    // smem store offsets (fixed per thread)
    const int aS0 = ATRANS ? (idx0 >> 5) * 136 + (idx0 & 31) * 4
                           : (idx0 >> 2) * 20  + (idx0 & 3)  * 4;
    const int aS1 = ATRANS ? (idx1 >> 5) * 136 + (idx1 & 31) * 4
                           : (idx1 >> 2) * 20  + (idx1 & 3)  * 4;
    const int bS0 = BTRANS ? (idx0 >> 5) * 136 + (idx0 & 31) * 4
                           : (idx0 >> 2) * 20  + (idx0 & 3)  * 4;
    const int bS1 = BTRANS ? (idx1 >> 5) * 136 + (idx1 & 31) * 4
                           : (idx1 >> 2) * 20  + (idx1 & 3)  * 4;

    float acc[4][4][4];
#pragma unroll
    for (int i = 0; i < 4; i++)
#pragma unroll
        for (int j = 0; j < 4; j++)
#pragma unroll
            for (int e = 0; e < 4; e++) acc[i][j][e] = 0.f;

    float4 stA0, stA1, stB0, stB1;            // staging registers
    float colacc[4] = {0.f, 0.f, 0.f, 0.f};   // EPI4: partial column sums of attn

#define LDG_TILE(kit)                                                    \
    {                                                                    \
        long long ao = (long long)(kit) * aStep;                         \
        long long bo = (long long)(kit) * bStep;                         \
        stA0 = *(const float4*)(aP0 + ao);                               \
        stA1 = *(const float4*)(aP1 + ao);                               \
        stB0 = *(const float4*)(bP0 + bo);                               \
        stB1 = *(const float4*)(bP1 + bo);                               \
    }

#define STS_TILE(Aw, Bw)                                                 \
    {                                                                    \
        if (EPI == 4) {                                                  \
            colacc[0] += stA0.x + stA1.x;                                \
            colacc[1] += stA0.y + stA1.y;                                \
            colacc[2] += stA0.z + stA1.z;                                \
            colacc[3] += stA0.w + stA1.w;                                \
        }                                                                \
        *(float4*)&(Aw)[aS0] = cvt4(stA0);                               \
        *(float4*)&(Aw)[aS1] = cvt4(stA1);                               \
        *(float4*)&(Bw)[bS0] = cvt4(stB0);                               \
        *(float4*)&(Bw)[bS1] = cvt4(stB1);                               \
    }

    // prologue
    LDG_TILE(0)
    STS_TILE(As0, Bs0)
    __syncthreads();

    const int kIters = K / 16;
    for (int kit = 0, buf = 0; kit < kIters; kit++, buf ^= 1) {
        const bool have_next = (kit + 1) < kIters;
        if (have_next) LDG_TILE(kit + 1)

        const float* Ab = buf ? As1 : As0;
        const float* Bb = buf ? Bs1 : Bs0;
#pragma unroll
        for (int ks = 0; ks < 16; ks += 8) {
            uint32_t a[4][4], b[4][2];
#pragma unroll
            for (int i = 0; i < 4; i++) {
                int rb = wm * 64 + i * 16 + grp;
                if (!ATRANS) {
                    a[i][0] = __float_as_uint(Ab[(rb    ) * 20 + ks + qid]);
                    a[i][1] = __float_as_uint(Ab[(rb + 8) * 20 + ks + qid]);
                    a[i][2] = __float_as_uint(Ab[(rb    ) * 20 + ks + 4 + qid]);
                    a[i][3] = __float_as_uint(Ab[(rb + 8) * 20 + ks + 4 + qid]);
                } else {
                    a[i][0] = __float_as_uint(Ab[(ks + qid    ) * 136 + rb]);
                    a[i][1] = __float_as_uint(Ab[(ks + qid    ) * 136 + rb + 8]);
                    a[i][2] = __float_as_uint(Ab[(ks + qid + 4) * 136 + rb]);
                    a[i][3] = __float_as_uint(Ab[(ks + qid + 4) * 136 + rb + 8]);
                }
            }
#pragma unroll
            for (int j = 0; j < 4; j++) {
                int nb = wn * 32 + j * 8 + grp;
                if (!BTRANS) {
                    b[j][0] = __float_as_uint(Bb[nb * 20 + ks + qid]);
                    b[j][1] = __float_as_uint(Bb[nb * 20 + ks + 4 + qid]);
                } else {
                    b[j][0] = __float_as_uint(Bb[(ks + qid    ) * 136 + nb]);
                    b[j][1] = __float_as_uint(Bb[(ks + qid + 4) * 136 + nb]);
                }
            }
#pragma unroll
            for (int i = 0; i < 4; i++)
#pragma unroll
                for (int j = 0; j < 4; j++) {
                    asm volatile(
                        "mma.sync.aligned.m16n8k8.row.col.f32.tf32.tf32.f32 "
                        "{%0,%1,%2,%3}, {%4,%5,%6,%7}, {%8,%9}, {%0,%1,%2,%3};\n"
                        : "+f"(acc[i][j][0]), "+f"(acc[i][j][1]),
                          "+f"(acc[i][j][2]), "+f"(acc[i][j][3])
                        : "r"(a[i][0]), "r"(a[i][1]), "r"(a[i][2]), "r"(a[i][3]),
                          "r"(b[j][0]), "r"(b[j][1]));
                }
        }
        if (have_next) {
            if (buf) STS_TILE(As0, Bs0)
            else     STS_TILE(As1, Bs1)
        }
        __syncthreads();
    }
#undef LDG_TILE
#undef STS_TILE

    // ---- EPI4: reduce column sums -> rscale in smem ----
    if (EPI == 4) {
        float* red = As0;      // 8 groups x 128 columns (first 1024 floats)
        const int g  = t >> 5;
        const int cq = (t & 31) * 4;
        red[g * 128 + cq + 0] = colacc[0];
        red[g * 128 + cq + 1] = colacc[1];
        red[g * 128 + cq + 2] = colacc[2];
        red[g * 128 + cq + 3] = colacc[3];
        __syncthreads();
        if (t < 128) {
            float s = 0.f;
#pragma unroll
            for (int gg = 0; gg < 8; gg++) s += red[gg * 128 + t];
            rsc[t] = 1.f / (1e-9f + s);
        }
        __syncthreads();
    }

    // ---- epilogue: direct store ----
    float* Cz = C + (long long)z * sC;
#pragma unroll
    for (int i = 0; i < 4; i++) {
        int r0 = m0 + wm * 64 + i * 16 + grp;
        int r1 = r0 + 8;
#pragma unroll
        for (int j = 0; j < 4; j++) {
            int c = n0 + wn * 32 + j * 8 + qid * 2;
            float d0 = acc[i][j][0], d1 = acc[i][j][1];
            float d2 = acc[i][j][2], d3 = acc[i][j][3];
            float2 o0, o1;
            if (EPI == 0 || EPI == 5) {
                o0 = make_float2(d0, d1);
                o1 = make_float2(d2, d3);
            } else if (EPI == 1) {
                float s0 = p0[c], s1 = p0[c+1], h0 = p1[c], h1 = p1[c+1];
                o0.x = fmaxf(d0 * s0 + h0, 0.f);
                o0.y = fmaxf(d1 * s1 + h1, 0.f);
                o1.x = fmaxf(d2 * s0 + h0, 0.f);
                o1.y = fmaxf(d3 * s1 + h1, 0.f);
            } else if (EPI == 2) {
                float h0 = p0[c], h1 = p0[c+1];
                o0 = make_float2(d0 + h0, d1 + h1);
                o1 = make_float2(d2 + h0, d3 + h1);
            } else { // EPI == 4 : u = h - acc*rscale[row]
                float rsa = rsc[r0 - m0];
                float rsb = rsc[r1 - m0];
                const float* hpz = p2 + (long long)z * sC;
                o0.x = hpz[(long long)r0 * ldc + c    ] - d0 * rsa;
                o0.y = hpz[(long long)r0 * ldc + c + 1] - d1 * rsa;
                o1.x = hpz[(long long)r1 * ldc + c    ] - d2 * rsb;
                o1.y = hpz[(long long)r1 * ldc + c + 1] - d3 * rsb;
            }
            *(float2*)&Cz[(long long)r0 * ldc + c] = o0;
            *(float2*)&Cz[(long long)r1 * ldc + c] = o1;
        }
    }

    // ---- EPI5 off-diagonal: mirrored (transposed) store via smem staging ----
    if (EPI == 5 && m0 != n0) {
        float* sm_t = smem;   // 64 x 132 floats = 8448 <= 10240 available
#pragma unroll
        for (int half = 0; half < 2; half++) {
            __syncthreads();
            if (wm == half) {
#pragma unroll
                for (int i = 0; i < 4; i++) {
                    int rl = i * 16 + grp;
#pragma unroll
                    for (int j = 0; j < 4; j++) {
                        int c = wn * 32 + j * 8 + qid * 2;
                        sm_t[rl * 132 + c]           = acc[i][j][0];
                        sm_t[rl * 132 + c + 1]       = acc[i][j][1];
                        sm_t[(rl + 8) * 132 + c]     = acc[i][j][2];
                        sm_t[(rl + 8) * 132 + c + 1] = acc[i][j][3];
                    }
                }
            }
            __syncthreads();
            // write C[n0+c][m0 + half*64 + 0..63], coalesced float4
            int c   = t >> 1;
            int seg = (t & 1) * 32;
            float* dst = Cz + (long long)(n0 + c) * ldc + m0 + half * 64 + seg;
#pragma unroll
            for (int s = 0; s < 32; s += 4) {
                float4 o;
                o.x = sm_t[(seg + s + 0) * 132 + c];
                o.y = sm_t[(seg + s + 1) * 132 + c];
                o.z = sm_t[(seg + s + 2) * 132 + c];
                o.w = sm_t[(seg + s + 3) * 132 + c];
                *(float4*)(dst + s) = o;
            }
        }
    }
}

// ---------------- softmax over last dim, one block per row (2048 elems) ----------
__global__ void softmax_rows(float* __restrict__ attn)
{
    __shared__ float red[256];
    float* p = attn + (long long)blockIdx.x * NN;
    const int t = threadIdx.x;
    float v[8];
    float mx = -1e30f;
#pragma unroll
    for (int i = 0; i < 8; i++) { v[i] = p[t + i*256]; mx = fmaxf(mx, v[i]); }
    red[t] = mx; __syncthreads();
    for (int s = 128; s > 0; s >>= 1) {
        if (t < s) red[t] = fmaxf(red[t], red[t + s]);
        __syncthreads();
    }
    mx = red[0]; __syncthreads();
    float sum = 0.f;
#pragma unroll
    for (int i = 0; i < 8; i++) { v[i] = __expf(v[i] - mx); sum += v[i]; }
    red[t] = sum; __syncthreads();
    for (int s = 128; s > 0; s >>= 1) {
        if (t < s) red[t] += red[t + s];
        __syncthreads();
    }
    float inv = 1.f / red[0];
#pragma unroll
    for (int i = 0; i < 8; i++) p[t + i*256] = v[i] * inv;
}

// ---------------- out[b,c,i] = h[b,i,c] + t[b,i,c]  (transpose via smem) ---------
__global__ void trans_add(const float* __restrict__ h, const float* __restrict__ tt,
                          float* __restrict__ out)
{
    __shared__ float sh[32][33];
    const int b  = blockIdx.z;
    const int i0 = blockIdx.x * 32, c0 = blockIdx.y * 32;
    const int tx = threadIdx.x, ty = threadIdx.y;   // 32 x 8
#pragma unroll
    for (int r = 0; r < 4; r++) {
        int i = i0 + ty + r * 8;
        long long idx = ((long long)b * NN + i) * CC + c0 + tx;
        sh[ty + r * 8][tx] = h[idx] + tt[idx];
    }
    __syncthreads();
#pragma unroll
    for (int r = 0; r < 4; r++) {
        int c = c0 + ty + r * 8;
        out[((long long)b * CC + c) * NN + i0 + tx] = sh[tx][ty + r * 8];
    }
}

// ==================================================================================
extern "C" void kernel_launch(void* const* d_in, const int* in_sizes, int n_in,
                              void* d_out, int out_size)
{
    const float* x   = (const float*)d_in[0];
    const float* w1  = (const float*)d_in[1];
    const float* w2  = (const float*)d_in[2];
    const float* wqk = (const float*)d_in[3];
    const float* wv  = (const float*)d_in[4];
    const float* bv  = (const float*)d_in[5];
    const float* wt  = (const float*)d_in[6];
    const float* bt  = (const float*)d_in[7];
    const float* bn1g = (const float*)d_in[8],  *bn1b = (const float*)d_in[9];
    const float* bn1m = (const float*)d_in[10], *bn1v = (const float*)d_in[11];
    const float* bn2g = (const float*)d_in[12], *bn2b = (const float*)d_in[13];
    const float* bn2m = (const float*)d_in[14], *bn2v = (const float*)d_in[15];
    const float* bn3g = (const float*)d_in[16], *bn3b = (const float*)d_in[17];
    const float* bn3m = (const float*)d_in[18], *bn3v = (const float*)d_in[19];

    float *h, *q, *v, *u, *attn, *bns, *bnh;
    cudaGetSymbolAddress((void**)&h, g_h);
    cudaGetSymbolAddress((void**)&q, g_q);
    cudaGetSymbolAddress((void**)&v, g_v);
    cudaGetSymbolAddress((void**)&u, g_u);
    cudaGetSymbolAddress((void**)&attn, g_attn);
    cudaGetSymbolAddress((void**)&bns, g_bnscale);
    cudaGetSymbolAddress((void**)&bnh, g_bnshift);

    bn_prep<<<1, 256>>>(bn1g, bn1b, bn1m, bn1v,
                        bn2g, bn2b, bn2m, bn2v,
                        bn3g, bn3b, bn3m, bn3v, bt);

    // h1 = relu(bn1(x @ w1^T))   (into q as temp)
    gemm_tc<1, false, false><<<dim3(CC/128, MTOT/128, 1), 256, SMEMB>>>(
        x, w1, q, CIN, CIN, CIN, CC, 0, 0, 0, bns, bnh, nullptr);

    // h = relu(bn2(h1 @ w2^T))
    gemm_tc<1, false, false><<<dim3(CC/128, MTOT/128, 1), 256, SMEMB>>>(
        q, w2, h, CC, CC, CC, CC, 0, 0, 0, bns + 256, bnh + 256, nullptr);

    // q = h @ wqk^T
    gemm_tc<0, false, false><<<dim3(CC/128, MTOT/128, 1), 256, SMEMB>>>(
        h, wqk, q, CC, CC, CC, CC, 0, 0, 0, nullptr, nullptr, nullptr);

    // v = h @ wv^T + bv
    gemm_tc<2, false, false><<<dim3(CC/128, MTOT/128, 1), 256, SMEMB>>>(
        h, wv, v, CC, CC, CC, CC, 0, 0, 0, bv, nullptr, nullptr);

    // energy[b,i,j] = q[b,i,:] . q[b,j,:]   (batched, SYMMETRIC: upper-tri blocks)
    gemm_tc<5, false, false><<<dim3(NPAIRS, 1, BB), 256, SMEMB>>>(
        q, q, attn, CC, CC, CC, NN,
        (long long)NN*CC, (long long)NN*CC, (long long)NN*NN,
        nullptr, nullptr, nullptr);

    // row softmax
    softmax_rows<<<MTOT, 256>>>(attn);

    // u[b,j,c] = h - (sum_i attn[i,j] v[i,c]) / (eps + sum_i attn[i,j])
    // colsum fused in-kernel from raw staged attn values
    gemm_tc<4, true, true><<<dim3(CC/128, NN/128, BB), 256, SMEMB>>>(
        attn, v, u, NN, NN, CC, CC,
        (long long)NN*NN, (long long)NN*CC, (long long)NN*CC,
        nullptr, nullptr, h);

    // t = relu(bn3(u @ wt^T + bt))   (into q as temp; bt folded into shift)
    gemm_tc<1, false, false><<<dim3(CC/128, MTOT/128, 1), 256, SMEMB>>>(
        u, wt, q, CC, CC, CC, CC, 0, 0, 0, bns + 512, bnh + 512, nullptr);

    // out[b,c,i] = h + t, transposed
    trans_add<<<dim3(NN/32, CC/32, BB), dim3(32, 8)>>>(h, q, (float*)d_out);
}